// round 14
// baseline (speedup 1.0000x reference)
#include <cuda_runtime.h>
#include <cstdint>
#include <cstddef>

// ---------------------------------------------------------------------------
// TokenEmbedding (sm_103, mma.sync TF32; tcgen05 not available in this build):
//   P0: pre-round proj_w / neg_w to tf32 (RNA) -> g_w1 / g_w2      (~5us)
//   P1: compact rows with negs==1 -> g_idx / g_cnt (+ pad)          (~10us)
//   A : GEMM1 (32768x768x2000) A=emb raw (HW RZ), B=g_w1; epilogue
//       bias + 5 tables, store RNA-rounded -> g_x
//   B : GEMM2 over compacted rows only -> g_y
//   C : row select on negs + LayerNorm -> d_out
// R11: tile body restructured to BATCH all 48 fragment LDS (both kk steps)
// before the 32 MMAs. R5/R8/R9/R10 all pinned tensor ~40% with per-kk
// load->mma chains; the batch removes the serialized 29-cyc LDS windows and
// lets ptxas interleave kk=1 loads under kk=0 MMAs.
// ---------------------------------------------------------------------------

namespace {
constexpr int M_ROWS = 64 * 512;   // 32768
constexpr int D_ENT  = 2000;
constexpr int H_DIM  = 768;

constexpr int BM = 128, BN = 128, BK = 16;
constexpr int LDSM = BK + 4;            // 20 floats/row: conflict-free + 16B-aligned
constexpr int STAGES = 5;
constexpr int STAGE_FLOATS = (BM + BN) * LDSM;          // 5120
constexpr int SMEM_BYTES   = STAGES * STAGE_FLOATS * 4; // 102400
}

// scratch (allocation-free rule: __device__ globals)
__device__ float g_x[(size_t)M_ROWS * H_DIM];   // GEMM1 out, tf32-rounded
__device__ float g_y[(size_t)M_ROWS * H_DIM];   // GEMM2 out (negs==1 rows valid)
__device__ float g_w1[(size_t)H_DIM * D_ENT];   // proj_w, tf32 RNA
__device__ float g_w2[(size_t)H_DIM * H_DIM];   // neg_w,  tf32 RNA
__device__ int   g_idx[M_ROWS];
__device__ int   g_cnt;

__device__ __forceinline__ uint32_t smem_u32(const void* p) {
    uint32_t a;
    asm("{ .reg .u64 t; cvta.to.shared.u64 t, %1; cvt.u32.u64 %0, t; }" : "=r"(a) : "l"(p));
    return a;
}
__device__ __forceinline__ uint32_t f2tf32(float x) {
    uint32_t r;
    asm("cvt.rna.tf32.f32 %0, %1;" : "=r"(r) : "f"(x));
    return r;
}
__device__ __forceinline__ void mma_tf32(float c[4], const uint32_t a[4], const uint32_t b[2]) {
    asm volatile(
        "mma.sync.aligned.m16n8k8.row.col.f32.tf32.tf32.f32 "
        "{%0,%1,%2,%3}, {%4,%5,%6,%7}, {%8,%9}, {%0,%1,%2,%3};"
        : "+f"(c[0]), "+f"(c[1]), "+f"(c[2]), "+f"(c[3])
        : "r"(a[0]), "r"(a[1]), "r"(a[2]), "r"(a[3]), "r"(b[0]), "r"(b[1]));
}
__device__ __forceinline__ void cp16(uint32_t dst, const void* src) {
    asm volatile("cp.async.cg.shared.global [%0], [%1], 16;" :: "r"(dst), "l"(src));
}

// ---------------- prepass kernels ----------------
__global__ void round_w_kernel(const float* __restrict__ src, float* __restrict__ dst, int n4) {
    const int i = blockIdx.x * blockDim.x + threadIdx.x;
    if (i >= n4) return;
    float4 v = reinterpret_cast<const float4*>(src)[i];
    v.x = __uint_as_float(f2tf32(v.x)); v.y = __uint_as_float(f2tf32(v.y));
    v.z = __uint_as_float(f2tf32(v.z)); v.w = __uint_as_float(f2tf32(v.w));
    reinterpret_cast<float4*>(dst)[i] = v;
}
__global__ void zero_cnt_kernel() { g_cnt = 0; }
__global__ void compact_kernel(const int* __restrict__ negs) {
    const int r = blockIdx.x * blockDim.x + threadIdx.x;
    if (r < M_ROWS && negs[r] == 1) {
        const int s = atomicAdd(&g_cnt, 1);
        g_idx[s] = r;
    }
}
__global__ void pad_idx_kernel() {
    const int c = g_cnt;
    const int padded = (c + BM - 1) & ~(BM - 1);
    const int fill = (c > 0) ? g_idx[0] : 0;
    for (int i = c + (int)threadIdx.x; i < padded; i += (int)blockDim.x) g_idx[i] = fill;
}

// ---------------- GEMM ----------------
// C[m][n] = sum_k A[m][k] * W[n][k]; K-major; dims divide tiles exactly.
template <int KDIM, bool FIRST>
__global__ __launch_bounds__(256, 2)
void gemm_tf32_kernel(const float* __restrict__ Ain,
                      const float* __restrict__ Bw,
                      const float* __restrict__ bias,
                      const int* __restrict__ i_nt, const int* __restrict__ i_ly,
                      const int* __restrict__ i_op, const int* __restrict__ i_id,
                      const int* __restrict__ i_od,
                      const float* __restrict__ te, const float* __restrict__ le,
                      const float* __restrict__ oe, const float* __restrict__ ie,
                      const float* __restrict__ ode)
{
    const int bm = blockIdx.y * BM;
    if (!FIRST && bm >= g_cnt) return;          // compacted-row early exit

    extern __shared__ float smem[];
    const uint32_t sbase = smem_u32(smem);

    const float* A = FIRST ? Ain : g_x;
    float* Cout    = FIRST ? g_x : g_y;

    const int bn = blockIdx.x * BN;
    const int tid  = threadIdx.x;
    const int wid  = tid >> 5;
    const int lane = tid & 31;
    const int warpM = (wid & 3) * 32;   // 4 warps along M
    const int warpN = (wid >> 2) * 64;  // 2 warps along N
    const int grp = lane >> 2;          // 0..7
    const int q   = lane & 3;           // 0..3

    float c[2][8][4];
    #pragma unroll
    for (int i = 0; i < 2; i++)
        #pragma unroll
        for (int j = 0; j < 8; j++)
            #pragma unroll
            for (int k = 0; k < 4; k++) c[i][j][k] = 0.f;

    // cp.async staging map: 256 threads x 4 x 16B per stage (A 2, B 2)
    const int row0 = tid >> 2;             // 0..63
    const int cb   = (tid & 3) * 16;       // byte col offset in smem row
    const int kcol = (tid & 3) * 4;        // float col offset in gmem

    size_t arow[2];
    #pragma unroll
    for (int i = 0; i < 2; i++) {
        const int r = bm + row0 + i * 64;
        arow[i] = FIRST ? (size_t)r : (size_t)g_idx[r];
    }

    auto ISSUE = [&](int kt, int s) {
        const uint32_t aB = sbase + (uint32_t)s * (STAGE_FLOATS * 4);
        const uint32_t bB = aB + BM * LDSM * 4;
        const int k0 = kt * BK + kcol;
        #pragma unroll
        for (int i = 0; i < 2; i++) {
            const int r = row0 + i * 64;
            cp16(aB + r * (LDSM * 4) + cb, A  + arow[i] * KDIM + k0);
            cp16(bB + r * (LDSM * 4) + cb, Bw + (size_t)(bn + r) * KDIM + k0);
        }
        asm volatile("cp.async.commit_group;" ::: "memory");
    };

    constexpr int KT = KDIM / BK;          // 125 or 48 (>= STAGES-1)
    #pragma unroll
    for (int kt = 0; kt < STAGES - 1; ++kt) ISSUE(kt, kt);

    int cs = 0;                 // compute stage
    int is_ = STAGES - 1;       // next issue stage

    // hoisted lane bases (per-fragment addressing is compile-time offsets)
    const int aoff = (warpM + grp) * LDSM + q;
    const int boff = (warpN + grp) * LDSM + q;

    #pragma unroll 1
    for (int kt = 0; kt < KT; ++kt) {
        if (kt + STAGES - 1 < KT)
            asm volatile("cp.async.wait_group %0;" :: "n"(STAGES - 2) : "memory");
        else
            asm volatile("cp.async.wait_group 0;" ::: "memory");
        __syncthreads();

        if (kt + STAGES - 1 < KT) {
            ISSUE(kt + STAGES - 1, is_);
            is_ = (is_ + 1 == STAGES) ? 0 : is_ + 1;
        }

        const float* as = smem + cs * STAGE_FLOATS;
        const float* bs = as + BM * LDSM;
        cs = (cs + 1 == STAGES) ? 0 : cs + 1;

        const float* ap = as + aoff;
        const float* bp = bs + boff;

        // ---- batched fragment loads: all 48 LDS independent, issued first ----
        uint32_t af[2][2][4], bf[2][8][2];
        #pragma unroll
        for (int kk = 0; kk < 2; ++kk) {
            #pragma unroll
            for (int mt = 0; mt < 2; ++mt) {
                af[kk][mt][0] = __float_as_uint(ap[(mt * 16) * LDSM + kk * 8]);
                af[kk][mt][1] = __float_as_uint(ap[(mt * 16 + 8) * LDSM + kk * 8]);
                af[kk][mt][2] = __float_as_uint(ap[(mt * 16) * LDSM + kk * 8 + 4]);
                af[kk][mt][3] = __float_as_uint(ap[(mt * 16 + 8) * LDSM + kk * 8 + 4]);
            }
            #pragma unroll
            for (int nt = 0; nt < 8; ++nt) {
                bf[kk][nt][0] = __float_as_uint(bp[(nt * 8) * LDSM + kk * 8]);
                bf[kk][nt][1] = __float_as_uint(bp[(nt * 8) * LDSM + kk * 8 + 4]);
            }
        }
        // ---- then all 32 MMAs ----
        #pragma unroll
        for (int kk = 0; kk < 2; ++kk)
            #pragma unroll
            for (int mt = 0; mt < 2; ++mt)
                #pragma unroll
                for (int nt = 0; nt < 8; ++nt)
                    mma_tf32(c[mt][nt], af[kk][mt], bf[kk][nt]);
    }

    // epilogue
    #pragma unroll
    for (int mt = 0; mt < 2; ++mt) {
        #pragma unroll
        for (int half = 0; half < 2; ++half) {
            const int mloc = bm + warpM + mt * 16 + grp + half * 8;
            const int m = FIRST ? mloc : g_idx[mloc];
            const float *tep = nullptr, *lep = nullptr, *oep = nullptr,
                        *iep = nullptr, *odp = nullptr;
            if (FIRST) {
                tep = te  + (size_t)i_nt[m] * H_DIM;
                lep = le  + (size_t)i_ly[m] * H_DIM;
                oep = oe  + (size_t)i_op[m] * H_DIM;
                iep = ie  + (size_t)i_id[m] * H_DIM;
                odp = ode + (size_t)i_od[m] * H_DIM;
            }
            float* outrow = Cout + (size_t)m * H_DIM;
            #pragma unroll
            for (int nt = 0; nt < 8; ++nt) {
                const int n0 = bn + warpN + nt * 8 + q * 2;   // even -> 8B aligned
                const float2 bb = *reinterpret_cast<const float2*>(bias + n0);
                float v0 = c[mt][nt][half * 2 + 0] + bb.x;
                float v1 = c[mt][nt][half * 2 + 1] + bb.y;
                if (FIRST) {
                    const float2 t0 = *reinterpret_cast<const float2*>(tep + n0);
                    const float2 t1 = *reinterpret_cast<const float2*>(lep + n0);
                    const float2 t2 = *reinterpret_cast<const float2*>(oep + n0);
                    const float2 t3 = *reinterpret_cast<const float2*>(iep + n0);
                    const float2 t4 = *reinterpret_cast<const float2*>(odp + n0);
                    v0 += t0.x + t1.x + t2.x + t3.x + t4.x;
                    v1 += t0.y + t1.y + t2.y + t3.y + t4.y;
                    v0 = __uint_as_float(f2tf32(v0));   // GEMM2 consumes cvt-free
                    v1 = __uint_as_float(f2tf32(v1));
                }
                *reinterpret_cast<float2*>(outrow + n0) = make_float2(v0, v1);
            }
        }
    }
}

// Stage C: warp-per-row select + LayerNorm (H=768 = 24 * 32)
__global__ __launch_bounds__(256)
void ln_select_kernel(const int* __restrict__ negs,
                      const float* __restrict__ lg, const float* __restrict__ lb,
                      float* __restrict__ out)
{
    const int row  = (int)((blockIdx.x * blockDim.x + threadIdx.x) >> 5);
    const int lane = threadIdx.x & 31;
    if (row >= M_ROWS) return;

    const float* src = (negs[row] == 1 ? g_y : g_x) + (size_t)row * H_DIM;

    float v[24];
    float s = 0.f;
    #pragma unroll
    for (int i = 0; i < 24; i++) { v[i] = src[lane + i * 32]; s += v[i]; }
    #pragma unroll
    for (int o = 16; o; o >>= 1) s += __shfl_xor_sync(0xffffffffu, s, o);
    const float mean = s * (1.f / 768.f);

    float vs = 0.f;
    #pragma unroll
    for (int i = 0; i < 24; i++) { const float d = v[i] - mean; vs += d * d; }
    #pragma unroll
    for (int o = 16; o; o >>= 1) vs += __shfl_xor_sync(0xffffffffu, vs, o);
    const float inv = rsqrtf(vs * (1.f / 768.f) + 1e-12f);

    float* orow = out + (size_t)row * H_DIM;
    #pragma unroll
    for (int i = 0; i < 24; i++) {
        const int h = lane + i * 32;
        orow[h] = (v[i] - mean) * inv * lg[h] + lb[h];
    }
}

extern "C" void kernel_launch(void* const* d_in, const int* in_sizes, int n_in,
                              void* d_out, int out_size)
{
    const float* emb = (const float*)d_in[0];
    const int*   nt  = (const int*)d_in[1];
    const int*   ly  = (const int*)d_in[2];
    const int*   op  = (const int*)d_in[3];
    const int*   id  = (const int*)d_in[4];
    const int*   od  = (const int*)d_in[5];
    const int*   ng  = (const int*)d_in[6];
    const float* te  = (const float*)d_in[7];
    const float* le  = (const float*)d_in[8];
    const float* oe  = (const float*)d_in[9];
    const float* ie  = (const float*)d_in[10];
    const float* ode = (const float*)d_in[11];
    const float* pw  = (const float*)d_in[12];
    const float* pb  = (const float*)d_in[13];
    const float* nw  = (const float*)d_in[14];
    const float* nb  = (const float*)d_in[15];
    const float* lg  = (const float*)d_in[16];
    const float* lb  = (const float*)d_in[17];
    float* out = (float*)d_out;

    cudaFuncSetAttribute(gemm_tf32_kernel<D_ENT, true>,
                         cudaFuncAttributeMaxDynamicSharedMemorySize, SMEM_BYTES);
    cudaFuncSetAttribute(gemm_tf32_kernel<H_DIM, false>,
                         cudaFuncAttributeMaxDynamicSharedMemorySize, SMEM_BYTES);

    float *w1p, *w2p;
    cudaGetSymbolAddress((void**)&w1p, g_w1);
    cudaGetSymbolAddress((void**)&w2p, g_w2);

    // P0: weight pre-rounding (RNA)
    {
        const int n1 = H_DIM * D_ENT / 4, n2 = H_DIM * H_DIM / 4;
        round_w_kernel<<<(n1 + 255) / 256, 256>>>(pw, w1p, n1);
        round_w_kernel<<<(n2 + 255) / 256, 256>>>(nw, w2p, n2);
    }
    // P1: row compaction on negs
    zero_cnt_kernel<<<1, 1>>>();
    compact_kernel<<<M_ROWS / 256, 256>>>(ng);
    pad_idx_kernel<<<1, 128>>>();

    // x-fastest over N-blocks: wave shares each A row-block across all
    // 6 N-blocks -> A hits L2 after first touch; weights stay L2-resident.
    dim3 grid(H_DIM / BN, M_ROWS / BM);   // (6, 256)

    gemm_tf32_kernel<D_ENT, true><<<grid, 256, SMEM_BYTES>>>(
        emb, w1p, pb, nt, ly, op, id, od, te, le, oe, ie, ode);

    gemm_tf32_kernel<H_DIM, false><<<grid, 256, SMEM_BYTES>>>(
        nullptr, w2p, nb,
        nullptr, nullptr, nullptr, nullptr, nullptr,
        nullptr, nullptr, nullptr, nullptr, nullptr);

    ln_select_kernel<<<(M_ROWS * 32) / 256, 256>>>(ng, lg, lb, out);
}

// round 15
// speedup vs baseline: 1.0007x; 1.0007x over previous
#include <cuda_runtime.h>
#include <cstdint>
#include <cstddef>

// ---------------------------------------------------------------------------
// TokenEmbedding (sm_103, mma.sync TF32; tcgen05 not available in this build):
//   P0: pre-round proj_w / neg_w to tf32 (RNA) -> g_w1 / g_w2      (~5us)
//   P1: compact rows with negs==1 -> g_idx / g_cnt (+ pad)          (~10us)
//   A : GEMM1 (32768x768x2000) A=emb raw (HW RZ), B=g_w1; epilogue
//       bias + 5 tables, store RNA-rounded -> g_x
//   B : GEMM2 over compacted rows only -> g_y
//   C : row select on negs + LayerNorm -> d_out
// R11: tile body restructured to BATCH all 48 fragment LDS (both kk steps)
// before the 32 MMAs. R5/R8/R9/R10 all pinned tensor ~40% with per-kk
// load->mma chains; the batch removes the serialized 29-cyc LDS windows and
// lets ptxas interleave kk=1 loads under kk=0 MMAs.
// ---------------------------------------------------------------------------

namespace {
constexpr int M_ROWS = 64 * 512;   // 32768
constexpr int D_ENT  = 2000;
constexpr int H_DIM  = 768;

constexpr int BM = 128, BN = 128, BK = 16;
constexpr int LDSM = BK + 4;            // 20 floats/row: conflict-free + 16B-aligned
constexpr int STAGES = 5;
constexpr int STAGE_FLOATS = (BM + BN) * LDSM;          // 5120
constexpr int SMEM_BYTES   = STAGES * STAGE_FLOATS * 4; // 102400
}

// scratch (allocation-free rule: __device__ globals)
__device__ float g_x[(size_t)M_ROWS * H_DIM];   // GEMM1 out, tf32-rounded
__device__ float g_y[(size_t)M_ROWS * H_DIM];   // GEMM2 out (negs==1 rows valid)
__device__ float g_w1[(size_t)H_DIM * D_ENT];   // proj_w, tf32 RNA
__device__ float g_w2[(size_t)H_DIM * H_DIM];   // neg_w,  tf32 RNA
__device__ int   g_idx[M_ROWS];
__device__ int   g_cnt;

__device__ __forceinline__ uint32_t smem_u32(const void* p) {
    uint32_t a;
    asm("{ .reg .u64 t; cvta.to.shared.u64 t, %1; cvt.u32.u64 %0, t; }" : "=r"(a) : "l"(p));
    return a;
}
__device__ __forceinline__ uint32_t f2tf32(float x) {
    uint32_t r;
    asm("cvt.rna.tf32.f32 %0, %1;" : "=r"(r) : "f"(x));
    return r;
}
__device__ __forceinline__ void mma_tf32(float c[4], const uint32_t a[4], const uint32_t b[2]) {
    asm volatile(
        "mma.sync.aligned.m16n8k8.row.col.f32.tf32.tf32.f32 "
        "{%0,%1,%2,%3}, {%4,%5,%6,%7}, {%8,%9}, {%0,%1,%2,%3};"
        : "+f"(c[0]), "+f"(c[1]), "+f"(c[2]), "+f"(c[3])
        : "r"(a[0]), "r"(a[1]), "r"(a[2]), "r"(a[3]), "r"(b[0]), "r"(b[1]));
}
__device__ __forceinline__ void cp16(uint32_t dst, const void* src) {
    asm volatile("cp.async.cg.shared.global [%0], [%1], 16;" :: "r"(dst), "l"(src));
}

// ---------------- prepass kernels ----------------
__global__ void round_w_kernel(const float* __restrict__ src, float* __restrict__ dst, int n4) {
    const int i = blockIdx.x * blockDim.x + threadIdx.x;
    if (i >= n4) return;
    float4 v = reinterpret_cast<const float4*>(src)[i];
    v.x = __uint_as_float(f2tf32(v.x)); v.y = __uint_as_float(f2tf32(v.y));
    v.z = __uint_as_float(f2tf32(v.z)); v.w = __uint_as_float(f2tf32(v.w));
    reinterpret_cast<float4*>(dst)[i] = v;
}
__global__ void zero_cnt_kernel() { g_cnt = 0; }
__global__ void compact_kernel(const int* __restrict__ negs) {
    const int r = blockIdx.x * blockDim.x + threadIdx.x;
    if (r < M_ROWS && negs[r] == 1) {
        const int s = atomicAdd(&g_cnt, 1);
        g_idx[s] = r;
    }
}
__global__ void pad_idx_kernel() {
    const int c = g_cnt;
    const int padded = (c + BM - 1) & ~(BM - 1);
    const int fill = (c > 0) ? g_idx[0] : 0;
    for (int i = c + (int)threadIdx.x; i < padded; i += (int)blockDim.x) g_idx[i] = fill;
}

// ---------------- GEMM ----------------
// C[m][n] = sum_k A[m][k] * W[n][k]; K-major; dims divide tiles exactly.
template <int KDIM, bool FIRST>
__global__ __launch_bounds__(256, 2)
void gemm_tf32_kernel(const float* __restrict__ Ain,
                      const float* __restrict__ Bw,
                      const float* __restrict__ bias,
                      const int* __restrict__ i_nt, const int* __restrict__ i_ly,
                      const int* __restrict__ i_op, const int* __restrict__ i_id,
                      const int* __restrict__ i_od,
                      const float* __restrict__ te, const float* __restrict__ le,
                      const float* __restrict__ oe, const float* __restrict__ ie,
                      const float* __restrict__ ode)
{
    const int bm = blockIdx.y * BM;
    if (!FIRST && bm >= g_cnt) return;          // compacted-row early exit

    extern __shared__ float smem[];
    const uint32_t sbase = smem_u32(smem);

    const float* A = FIRST ? Ain : g_x;
    float* Cout    = FIRST ? g_x : g_y;

    const int bn = blockIdx.x * BN;
    const int tid  = threadIdx.x;
    const int wid  = tid >> 5;
    const int lane = tid & 31;
    const int warpM = (wid & 3) * 32;   // 4 warps along M
    const int warpN = (wid >> 2) * 64;  // 2 warps along N
    const int grp = lane >> 2;          // 0..7
    const int q   = lane & 3;           // 0..3

    float c[2][8][4];
    #pragma unroll
    for (int i = 0; i < 2; i++)
        #pragma unroll
        for (int j = 0; j < 8; j++)
            #pragma unroll
            for (int k = 0; k < 4; k++) c[i][j][k] = 0.f;

    // cp.async staging map: 256 threads x 4 x 16B per stage (A 2, B 2)
    const int row0 = tid >> 2;             // 0..63
    const int cb   = (tid & 3) * 16;       // byte col offset in smem row
    const int kcol = (tid & 3) * 4;        // float col offset in gmem

    size_t arow[2];
    #pragma unroll
    for (int i = 0; i < 2; i++) {
        const int r = bm + row0 + i * 64;
        arow[i] = FIRST ? (size_t)r : (size_t)g_idx[r];
    }

    auto ISSUE = [&](int kt, int s) {
        const uint32_t aB = sbase + (uint32_t)s * (STAGE_FLOATS * 4);
        const uint32_t bB = aB + BM * LDSM * 4;
        const int k0 = kt * BK + kcol;
        #pragma unroll
        for (int i = 0; i < 2; i++) {
            const int r = row0 + i * 64;
            cp16(aB + r * (LDSM * 4) + cb, A  + arow[i] * KDIM + k0);
            cp16(bB + r * (LDSM * 4) + cb, Bw + (size_t)(bn + r) * KDIM + k0);
        }
        asm volatile("cp.async.commit_group;" ::: "memory");
    };

    constexpr int KT = KDIM / BK;          // 125 or 48 (>= STAGES-1)
    #pragma unroll
    for (int kt = 0; kt < STAGES - 1; ++kt) ISSUE(kt, kt);

    int cs = 0;                 // compute stage
    int is_ = STAGES - 1;       // next issue stage

    // hoisted lane bases (per-fragment addressing is compile-time offsets)
    const int aoff = (warpM + grp) * LDSM + q;
    const int boff = (warpN + grp) * LDSM + q;

    #pragma unroll 1
    for (int kt = 0; kt < KT; ++kt) {
        if (kt + STAGES - 1 < KT)
            asm volatile("cp.async.wait_group %0;" :: "n"(STAGES - 2) : "memory");
        else
            asm volatile("cp.async.wait_group 0;" ::: "memory");
        __syncthreads();

        if (kt + STAGES - 1 < KT) {
            ISSUE(kt + STAGES - 1, is_);
            is_ = (is_ + 1 == STAGES) ? 0 : is_ + 1;
        }

        const float* as = smem + cs * STAGE_FLOATS;
        const float* bs = as + BM * LDSM;
        cs = (cs + 1 == STAGES) ? 0 : cs + 1;

        const float* ap = as + aoff;
        const float* bp = bs + boff;

        // ---- batched fragment loads: all 48 LDS independent, issued first ----
        uint32_t af[2][2][4], bf[2][8][2];
        #pragma unroll
        for (int kk = 0; kk < 2; ++kk) {
            #pragma unroll
            for (int mt = 0; mt < 2; ++mt) {
                af[kk][mt][0] = __float_as_uint(ap[(mt * 16) * LDSM + kk * 8]);
                af[kk][mt][1] = __float_as_uint(ap[(mt * 16 + 8) * LDSM + kk * 8]);
                af[kk][mt][2] = __float_as_uint(ap[(mt * 16) * LDSM + kk * 8 + 4]);
                af[kk][mt][3] = __float_as_uint(ap[(mt * 16 + 8) * LDSM + kk * 8 + 4]);
            }
            #pragma unroll
            for (int nt = 0; nt < 8; ++nt) {
                bf[kk][nt][0] = __float_as_uint(bp[(nt * 8) * LDSM + kk * 8]);
                bf[kk][nt][1] = __float_as_uint(bp[(nt * 8) * LDSM + kk * 8 + 4]);
            }
        }
        // ---- then all 32 MMAs ----
        #pragma unroll
        for (int kk = 0; kk < 2; ++kk)
            #pragma unroll
            for (int mt = 0; mt < 2; ++mt)
                #pragma unroll
                for (int nt = 0; nt < 8; ++nt)
                    mma_tf32(c[mt][nt], af[kk][mt], bf[kk][nt]);
    }

    // epilogue
    #pragma unroll
    for (int mt = 0; mt < 2; ++mt) {
        #pragma unroll
        for (int half = 0; half < 2; ++half) {
            const int mloc = bm + warpM + mt * 16 + grp + half * 8;
            const int m = FIRST ? mloc : g_idx[mloc];
            const float *tep = nullptr, *lep = nullptr, *oep = nullptr,
                        *iep = nullptr, *odp = nullptr;
            if (FIRST) {
                tep = te  + (size_t)i_nt[m] * H_DIM;
                lep = le  + (size_t)i_ly[m] * H_DIM;
                oep = oe  + (size_t)i_op[m] * H_DIM;
                iep = ie  + (size_t)i_id[m] * H_DIM;
                odp = ode + (size_t)i_od[m] * H_DIM;
            }
            float* outrow = Cout + (size_t)m * H_DIM;
            #pragma unroll
            for (int nt = 0; nt < 8; ++nt) {
                const int n0 = bn + warpN + nt * 8 + q * 2;   // even -> 8B aligned
                const float2 bb = *reinterpret_cast<const float2*>(bias + n0);
                float v0 = c[mt][nt][half * 2 + 0] + bb.x;
                float v1 = c[mt][nt][half * 2 + 1] + bb.y;
                if (FIRST) {
                    const float2 t0 = *reinterpret_cast<const float2*>(tep + n0);
                    const float2 t1 = *reinterpret_cast<const float2*>(lep + n0);
                    const float2 t2 = *reinterpret_cast<const float2*>(oep + n0);
                    const float2 t3 = *reinterpret_cast<const float2*>(iep + n0);
                    const float2 t4 = *reinterpret_cast<const float2*>(odp + n0);
                    v0 += t0.x + t1.x + t2.x + t3.x + t4.x;
                    v1 += t0.y + t1.y + t2.y + t3.y + t4.y;
                    v0 = __uint_as_float(f2tf32(v0));   // GEMM2 consumes cvt-free
                    v1 = __uint_as_float(f2tf32(v1));
                }
                *reinterpret_cast<float2*>(outrow + n0) = make_float2(v0, v1);
            }
        }
    }
}

// Stage C: warp-per-row select + LayerNorm (H=768 = 24 * 32)
__global__ __launch_bounds__(256)
void ln_select_kernel(const int* __restrict__ negs,
                      const float* __restrict__ lg, const float* __restrict__ lb,
                      float* __restrict__ out)
{
    const int row  = (int)((blockIdx.x * blockDim.x + threadIdx.x) >> 5);
    const int lane = threadIdx.x & 31;
    if (row >= M_ROWS) return;

    const float* src = (negs[row] == 1 ? g_y : g_x) + (size_t)row * H_DIM;

    float v[24];
    float s = 0.f;
    #pragma unroll
    for (int i = 0; i < 24; i++) { v[i] = src[lane + i * 32]; s += v[i]; }
    #pragma unroll
    for (int o = 16; o; o >>= 1) s += __shfl_xor_sync(0xffffffffu, s, o);
    const float mean = s * (1.f / 768.f);

    float vs = 0.f;
    #pragma unroll
    for (int i = 0; i < 24; i++) { const float d = v[i] - mean; vs += d * d; }
    #pragma unroll
    for (int o = 16; o; o >>= 1) vs += __shfl_xor_sync(0xffffffffu, vs, o);
    const float inv = rsqrtf(vs * (1.f / 768.f) + 1e-12f);

    float* orow = out + (size_t)row * H_DIM;
    #pragma unroll
    for (int i = 0; i < 24; i++) {
        const int h = lane + i * 32;
        orow[h] = (v[i] - mean) * inv * lg[h] + lb[h];
    }
}

extern "C" void kernel_launch(void* const* d_in, const int* in_sizes, int n_in,
                              void* d_out, int out_size)
{
    const float* emb = (const float*)d_in[0];
    const int*   nt  = (const int*)d_in[1];
    const int*   ly  = (const int*)d_in[2];
    const int*   op  = (const int*)d_in[3];
    const int*   id  = (const int*)d_in[4];
    const int*   od  = (const int*)d_in[5];
    const int*   ng  = (const int*)d_in[6];
    const float* te  = (const float*)d_in[7];
    const float* le  = (const float*)d_in[8];
    const float* oe  = (const float*)d_in[9];
    const float* ie  = (const float*)d_in[10];
    const float* ode = (const float*)d_in[11];
    const float* pw  = (const float*)d_in[12];
    const float* pb  = (const float*)d_in[13];
    const float* nw  = (const float*)d_in[14];
    const float* nb  = (const float*)d_in[15];
    const float* lg  = (const float*)d_in[16];
    const float* lb  = (const float*)d_in[17];
    float* out = (float*)d_out;

    cudaFuncSetAttribute(gemm_tf32_kernel<D_ENT, true>,
                         cudaFuncAttributeMaxDynamicSharedMemorySize, SMEM_BYTES);
    cudaFuncSetAttribute(gemm_tf32_kernel<H_DIM, false>,
                         cudaFuncAttributeMaxDynamicSharedMemorySize, SMEM_BYTES);

    float *w1p, *w2p;
    cudaGetSymbolAddress((void**)&w1p, g_w1);
    cudaGetSymbolAddress((void**)&w2p, g_w2);

    // P0: weight pre-rounding (RNA)
    {
        const int n1 = H_DIM * D_ENT / 4, n2 = H_DIM * H_DIM / 4;
        round_w_kernel<<<(n1 + 255) / 256, 256>>>(pw, w1p, n1);
        round_w_kernel<<<(n2 + 255) / 256, 256>>>(nw, w2p, n2);
    }
    // P1: row compaction on negs
    zero_cnt_kernel<<<1, 1>>>();
    compact_kernel<<<M_ROWS / 256, 256>>>(ng);
    pad_idx_kernel<<<1, 128>>>();

    // x-fastest over N-blocks: wave shares each A row-block across all
    // 6 N-blocks -> A hits L2 after first touch; weights stay L2-resident.
    dim3 grid(H_DIM / BN, M_ROWS / BM);   // (6, 256)

    gemm_tf32_kernel<D_ENT, true><<<grid, 256, SMEM_BYTES>>>(
        emb, w1p, pb, nt, ly, op, id, od, te, le, oe, ie, ode);

    gemm_tf32_kernel<H_DIM, false><<<grid, 256, SMEM_BYTES>>>(
        nullptr, w2p, nb,
        nullptr, nullptr, nullptr, nullptr, nullptr,
        nullptr, nullptr, nullptr, nullptr, nullptr);

    ln_select_kernel<<<(M_ROWS * 32) / 256, 256>>>(ng, lg, lb, out);
}